// round 12
// baseline (speedup 1.0000x reference)
#include <cuda_runtime.h>

// Kalman filter, simple-form update, 2x4-block-per-lane layout.
// B=4096, T=200, S=8, M=2.
// 8 lanes per batch: lane (rp = row-pair 0..3, c = col half 0..1) owns
// P[2rp..2rp+1][4c..4c+3] (2x4 block). 4 batches per 32-lane warp,
// 1024 warps. Each broadcast matmul LDS serves TWO output rows and uses the
// full 128B crossbar width (8 distinct 16B groups across 4 batches x 2 halves).
// SMEM bank layout engineered per instruction:
//   WSF = 184 (== 24 mod 32); Pu split lo/hi at delta 36 (== 4 mod 8);
//   F in two 4-row blocks (A: rows 0-3 [lo|hi], B: rows 4-7 [hi|lo]) so the
//   own-chunk read is always at +0 and bank groups stay distinct.

namespace {
constexpr int Bb  = 4096;
constexpr int Tt  = 200;
constexpr int WSF = 184;
constexpr unsigned FULL = 0xffffffffu;
// per-batch SMEM float offsets
constexpr int OPUL = 0;    // Pu cols 0..3, row j at +j*4
constexpr int OPUH = 36;   // Pu cols 4..7
constexpr int OFA  = 68;   // F rows 0..3, 8 f/row, [lo|hi]
constexpr int OFB  = 104;  // F rows 4..7, 8 f/row, [hi|lo]
constexpr int OHPL = 136;  // (hp0,hp1) interleaved, cols 0..3
constexpr int OHPH = 148;  // cols 4..7
constexpr int OMU  = 156;  // updated mean (8)
constexpr int OMN  = 164;  // predicted mean (8)
}

__global__ __launch_bounds__(32)
void kalman_kernel(const float* __restrict__ gy,      // [B,T,2]
                   const float* __restrict__ gF,      // [B,T,8,8]
                   const float* __restrict__ gH,      // [B,T,2,8]
                   const float* __restrict__ gQ,      // [8,8]
                   const float* __restrict__ gR,      // [2,2]
                   const float* __restrict__ gMean0,  // [B,8]
                   const float* __restrict__ gCov0,   // [8,8]
                   float* __restrict__ oMean,         // [B,T,8]
                   float* __restrict__ oCov)          // [B,T,8,8]
{
    __shared__ __align__(16) float sw[4 * WSF];
    const int lane = threadIdx.x;
    const int lb   = lane >> 3;          // batch within warp (0..3)
    const int c    = (lane >> 2) & 1;    // column half
    const int rp   = lane & 3;           // row pair
    const int ra   = 2 * rp;             // owned rows ra, ra+1
    const int cb   = 4 * c;              // own column base
    const int ob   = 4 - cb;             // other column base
    const int b    = blockIdx.x * 4 + lb;

    float* wsp = sw + lb * WSF;
    const int opu  = c ? OPUH : OPUL;    // own Pu half-block
    const int ohp  = c ? OHPH : OHPL;    // own HP half
    const int ofk  = c ? OFB  : OFA;     // F block holding own k-rows
    const int fblk = (rp < 2) ? OFA : OFB;           // block of own F rows
    const int fcof = (rp < 2) ? cb : ob;             // chunk offset in block
    const int frow = (rp & 1) * 16;                  // (ra&3)*8

    const float R00 = gR[0], R01 = gR[1], R10 = gR[2], R11 = gR[3];
    float Qa[4], Qb[4];
#pragma unroll
    for (int m = 0; m < 4; ++m) {
        Qa[m] = gQ[ra * 8 + cb + m];
        Qb[m] = gQ[(ra + 1) * 8 + cb + m];
    }

    float* omb = oMean + (size_t)b * Tt * 8;
    float* ocb = oCov  + (size_t)b * Tt * 64;

    // ---- init: own 2x4 block of P; t=0 outputs ----
    float pra[4], prb[4];
    {
        const float4 p0 = *(const float4*)(gCov0 + ra * 8 + cb);
        const float4 p1 = *(const float4*)(gCov0 + (ra + 1) * 8 + cb);
        pra[0]=p0.x; pra[1]=p0.y; pra[2]=p0.z; pra[3]=p0.w;
        prb[0]=p1.x; prb[1]=p1.y; prb[2]=p1.z; prb[3]=p1.w;
        *(float4*)(ocb + ra * 8 + cb)       = p0;
        *(float4*)(ocb + (ra + 1) * 8 + cb) = p1;
    }
    if (c == 0) {
        const float2 m0 = *(const float2*)(gMean0 + b * 8 + ra);
        *(float2*)(wsp + OMN + ra) = m0;
        *(float2*)(omb + ra)       = m0;
    }

    const float* Fb = gF + (size_t)b * Tt * 64;
    const float* Hb = gH + (size_t)b * Tt * 16;
    const float* yb = gy + (size_t)b * Tt * 2;

    // ---- prefetch step 0 ----
    float4 fA4 = *(const float4*)(Fb + ra * 8 + cb);        // F[ra][cb..]
    float4 fB4 = *(const float4*)(Fb + (ra + 1) * 8 + cb);  // F[ra+1][cb..]
    float4 hA  = *(const float4*)(Hb + cb);                 // H[0][cb..]
    float4 hC  = *(const float4*)(Hb + 8 + cb);             // H[1][cb..]
    float2 yv  = *(const float2*)(yb);

    __syncwarp();

    for (int t = 0; t < Tt - 1; ++t) {
        const float fa[4]  = {fA4.x, fA4.y, fA4.z, fA4.w};
        const float fbr[4] = {fB4.x, fB4.y, fB4.z, fB4.w};
        const float hao[4] = {hA.x, hA.y, hA.z, hA.w};
        const float hco[4] = {hC.x, hC.y, hC.z, hC.w};
        const float y0 = yv.x, y1 = yv.y;

        // prefetch next step
        {
            const float* Fn = Fb + (size_t)(t + 1) * 64;
            fA4 = *(const float4*)(Fn + ra * 8 + cb);
            fB4 = *(const float4*)(Fn + (ra + 1) * 8 + cb);
            const float* Hn = Hb + (size_t)(t + 1) * 16;
            hA = *(const float4*)(Hn + cb);
            hC = *(const float4*)(Hn + 8 + cb);
            yv = *(const float2*)(yb + (size_t)(t + 1) * 2);
        }

        // ---- phase 1 ----
        // store F quarters (block A [lo|hi], block B [hi|lo])
        *(float4*)(wsp + fblk + frow + fcof)     = make_float4(fa[0], fa[1], fa[2], fa[3]);
        *(float4*)(wsp + fblk + frow + 8 + fcof) = make_float4(fbr[0], fbr[1], fbr[2], fbr[3]);

        // HP partials for own rows (P symmetric: HP[m][r] = dot(H[m], P row r))
        float hp0a = 0.f, hp1a = 0.f, hp0b = 0.f, hp1b = 0.f;
#pragma unroll
        for (int m = 0; m < 4; ++m) {
            hp0a += hao[m] * pra[m];
            hp1a += hco[m] * pra[m];
            hp0b += hao[m] * prb[m];
            hp1b += hco[m] * prb[m];
        }
        hp0a += __shfl_xor_sync(FULL, hp0a, 4);
        hp1a += __shfl_xor_sync(FULL, hp1a, 4);
        hp0b += __shfl_xor_sync(FULL, hp0b, 4);
        hp1b += __shfl_xor_sync(FULL, hp1b, 4);
        if (c == 0)
            *(float4*)(wsp + ((rp < 2) ? OHPL : OHPH) + 4 * (rp & 1)) =
                make_float4(hp0a, hp1a, hp0b, hp1b);

        // residual partials (uses prev-step sMean, synced)
        float r0 = 0.f, r1 = 0.f;
        {
            const float4 mo = *(const float4*)(wsp + OMN + cb);
            float r0p = hao[0]*mo.x + hao[1]*mo.y + hao[2]*mo.z + hao[3]*mo.w;
            float r1p = hco[0]*mo.x + hco[1]*mo.y + hco[2]*mo.z + hco[3]*mo.w;
            r0 = y0 - (r0p + __shfl_xor_sync(FULL, r0p, 4));
            r1 = y1 - (r1p + __shfl_xor_sync(FULL, r1p, 4));
        }

        // other-half quarters of own F rows, from the c-partner lane
        float foa[4], fob[4];
#pragma unroll
        for (int m = 0; m < 4; ++m) {
            foa[m] = __shfl_xor_sync(FULL, fa[m], 4);
            fob[m] = __shfl_xor_sync(FULL, fbr[m], 4);
        }
        __syncwarp();  // sync A: sF, sHP visible

        // ---- phase 2: Smat, gains, P_u, mean_u ----
        float HP0o[4], HP1o[4];
        {
            const float4 u0 = *(const float4*)(wsp + ohp);
            const float4 u1 = *(const float4*)(wsp + ohp + 4);
            HP0o[0]=u0.x; HP1o[0]=u0.y; HP0o[1]=u0.z; HP1o[1]=u0.w;
            HP0o[2]=u1.x; HP1o[2]=u1.y; HP0o[3]=u1.z; HP1o[3]=u1.w;
        }
        float s00p = 0.f, s01p = 0.f, s10p = 0.f, s11p = 0.f;
#pragma unroll
        for (int m = 0; m < 4; ++m) {
            s00p += HP0o[m] * hao[m];
            s01p += HP0o[m] * hco[m];
            s10p += HP1o[m] * hao[m];
            s11p += HP1o[m] * hco[m];
        }
        const float s00 = R00 + s00p + __shfl_xor_sync(FULL, s00p, 4);
        const float s01 = R01 + s01p + __shfl_xor_sync(FULL, s01p, 4);
        const float s10 = R10 + s10p + __shfl_xor_sync(FULL, s10p, 4);
        const float s11 = R11 + s11p + __shfl_xor_sync(FULL, s11p, 4);
        const float inv = 1.0f / (s00 * s11 - s01 * s10);
        const float w0a = inv * ( s11 * hp0a - s01 * hp1a);
        const float w1a = inv * (-s10 * hp0a + s00 * hp1a);
        const float w0b = inv * ( s11 * hp0b - s01 * hp1b);
        const float w1b = inv * (-s10 * hp0b + s00 * hp1b);

        float pua[4], pub[4];
#pragma unroll
        for (int m = 0; m < 4; ++m) {
            pua[m] = pra[m] - w0a * HP0o[m] - w1a * HP1o[m];
            pub[m] = prb[m] - w0b * HP0o[m] - w1b * HP1o[m];
        }
        *(float4*)(wsp + opu + ra * 4)       = make_float4(pua[0], pua[1], pua[2], pua[3]);
        *(float4*)(wsp + opu + (ra + 1) * 4) = make_float4(pub[0], pub[1], pub[2], pub[3]);

        if (c == 0) {
            const float2 mpair = *(const float2*)(wsp + OMN + ra);
            *(float2*)(wsp + OMU + ra) =
                make_float2(mpair.x + w0a * r0 + w1a * r1,
                            mpair.y + w0b * r0 + w1b * r1);
        }
        __syncwarp();  // sync B: sPU, sMU visible; sMean reads done

        // ---- phase 3: predict ----
        // G rows ra, ra+1, own cols: one pass over Pu column-block
        float g0 = 0.f, g1 = 0.f, g2 = 0.f, g3 = 0.f;
        float e0 = 0.f, e1 = 0.f, e2 = 0.f, e3 = 0.f;
#pragma unroll
        for (int m = 0; m < 4; ++m) {           // j = cb+m, coeff = own F quarter
            const float4 pj = *(const float4*)(wsp + opu + (cb + m) * 4);
            g0 += fa[m]  * pj.x; g1 += fa[m]  * pj.y;
            g2 += fa[m]  * pj.z; g3 += fa[m]  * pj.w;
            e0 += fbr[m] * pj.x; e1 += fbr[m] * pj.y;
            e2 += fbr[m] * pj.z; e3 += fbr[m] * pj.w;
        }
#pragma unroll
        for (int m = 0; m < 4; ++m) {           // j = ob+m, coeff = fo quarter
            const float4 pj = *(const float4*)(wsp + opu + (ob + m) * 4);
            g0 += foa[m] * pj.x; g1 += foa[m] * pj.y;
            g2 += foa[m] * pj.z; g3 += foa[m] * pj.w;
            e0 += fob[m] * pj.x; e1 += fob[m] * pj.y;
            e2 += fob[m] * pj.z; e3 += fob[m] * pj.w;
        }
        // partner's G halves (G[r][other cols])
        const float x0 = __shfl_xor_sync(FULL, g0, 4);
        const float x1 = __shfl_xor_sync(FULL, g1, 4);
        const float x2 = __shfl_xor_sync(FULL, g2, 4);
        const float x3 = __shfl_xor_sync(FULL, g3, 4);
        const float z0 = __shfl_xor_sync(FULL, e0, 4);
        const float z1 = __shfl_xor_sync(FULL, e1, 4);
        const float z2 = __shfl_xor_sync(FULL, e2, 4);
        const float z3 = __shfl_xor_sync(FULL, e3, 4);

        // P'[r][cb+kk] = G_row . F[k][:] + Q  (own chunk at +0, other at +4)
        float pna[4], pnb[4];
#pragma unroll
        for (int kk = 0; kk < 4; ++kk) {
            const float4 qo = *(const float4*)(wsp + ofk + kk * 8);      // F[k][own]
            const float4 qt = *(const float4*)(wsp + ofk + kk * 8 + 4);  // F[k][other]
            pna[kk] = Qa[kk]
                    + g0*qo.x + g1*qo.y + g2*qo.z + g3*qo.w
                    + x0*qt.x + x1*qt.y + x2*qt.z + x3*qt.w;
            pnb[kk] = Qb[kk]
                    + e0*qo.x + e1*qo.y + e2*qo.z + e3*qo.w
                    + z0*qt.x + z1*qt.y + z2*qt.z + z3*qt.w;
        }
#pragma unroll
        for (int m = 0; m < 4; ++m) { pra[m] = pna[m]; prb[m] = pnb[m]; }

        *(float4*)(ocb + (size_t)(t + 1) * 64 + ra * 8 + cb) =
            make_float4(pna[0], pna[1], pna[2], pna[3]);
        *(float4*)(ocb + (size_t)(t + 1) * 64 + (ra + 1) * 8 + cb) =
            make_float4(pnb[0], pnb[1], pnb[2], pnb[3]);

        // mean predict (c == 0 lanes; they hold cols 0..3 own + 4..7 via fo)
        if (c == 0) {
            const float4 u0 = *(const float4*)(wsp + OMU);
            const float4 u1 = *(const float4*)(wsp + OMU + 4);
            const float mpa =
                  fa[0]*u0.x + fa[1]*u0.y + fa[2]*u0.z + fa[3]*u0.w
                + foa[0]*u1.x + foa[1]*u1.y + foa[2]*u1.z + foa[3]*u1.w;
            const float mpb =
                  fbr[0]*u0.x + fbr[1]*u0.y + fbr[2]*u0.z + fbr[3]*u0.w
                + fob[0]*u1.x + fob[1]*u1.y + fob[2]*u1.z + fob[3]*u1.w;
            *(float2*)(wsp + OMN + ra) = make_float2(mpa, mpb);
            *(float2*)(omb + (size_t)(t + 1) * 8 + ra) = make_float2(mpa, mpb);
        }
        __syncwarp();  // sync C: phase-3 reads done; sMean visible next iter
    }
}

extern "C" void kernel_launch(void* const* d_in, const int* in_sizes, int n_in,
                              void* d_out, int out_size)
{
    // metadata order: y, F, H, Q, R, init_mean, init_cov, n_step
    const float* gy     = (const float*)d_in[0];
    const float* gF     = (const float*)d_in[1];
    const float* gH     = (const float*)d_in[2];
    const float* gQ     = (const float*)d_in[3];
    const float* gR     = (const float*)d_in[4];
    const float* gMean0 = (const float*)d_in[5];
    const float* gCov0  = (const float*)d_in[6];
    (void)in_sizes; (void)n_in;

    float* oMean = (float*)d_out;                          // [B,T,8]
    float* oCov  = (float*)d_out + (size_t)Bb * Tt * 8;    // [B,T,8,8]
    (void)out_size;

    kalman_kernel<<<Bb / 4, 32>>>(gy, gF, gH, gQ, gR, gMean0, gCov0,
                                  oMean, oCov);
}